// round 8
// baseline (speedup 1.0000x reference)
#include <cuda_runtime.h>
#include <cuda_fp16.h>
#include <math_constants.h>

#define NN 50000
#define EE 850000

// ---------------- scratch (device globals; no allocation allowed) ----------
__device__ __half g_feat16[NN * 128];
__device__ float  g_h0[NN * 128];
__device__ float  g_h1[NN * 64];
__device__ float  g_el[NN * 2];
__device__ float  g_er[NN * 2];
__device__ int    g_src[EE];
__device__ int    g_dst[EE];
__device__ int    g_count[NN];
__device__ int    g_cursor[NN];
__device__ int    g_rowptr[NN + 1];
__device__ int    g_colsrc[EE];
__device__ int    g_bsum[64];
__device__ int    g_is64;

// ---------------- index width detection ------------------------------------
__global__ void detect_kernel(const unsigned* src_w, const unsigned* dst_w) {
    int i64 = 1;
    for (int k = 0; k < 16; k++) {
        if (src_w[2 * k + 1] != 0u) i64 = 0;
        if (dst_w[2 * k + 1] != 0u) i64 = 0;
    }
    g_is64 = i64;
}

// convert indices + histogram of dst
__global__ void hist_kernel(const void* src, const void* dst) {
    int i = blockIdx.x * blockDim.x + threadIdx.x;
    if (i >= EE) return;
    int s, d;
    if (g_is64) {
        s = (int)((const long long*)src)[i];
        d = (int)((const long long*)dst)[i];
    } else {
        s = ((const int*)src)[i];
        d = ((const int*)dst)[i];
    }
    g_src[i] = s;
    g_dst[i] = d;
    atomicAdd(&g_count[d], 1);
}

// ---------------- fast 3-phase exclusive scan -------------------------------
__global__ void scan_block_kernel() {
    __shared__ int wsum[32];
    int i = blockIdx.x * 1024 + threadIdx.x;
    int lane = threadIdx.x & 31, wid = threadIdx.x >> 5;
    int v = (i < NN) ? g_count[i] : 0;
    int incl = v;
#pragma unroll
    for (int off = 1; off < 32; off <<= 1) {
        int t = __shfl_up_sync(0xFFFFFFFFu, incl, off);
        if (lane >= off) incl += t;
    }
    if (lane == 31) wsum[wid] = incl;
    __syncthreads();
    if (wid == 0) {
        int s = wsum[lane];
        int si = s;
#pragma unroll
        for (int off = 1; off < 32; off <<= 1) {
            int t = __shfl_up_sync(0xFFFFFFFFu, si, off);
            if (lane >= off) si += t;
        }
        wsum[lane] = si - s;
        if (lane == 31) g_bsum[blockIdx.x] = si;
    }
    __syncthreads();
    if (i < NN) g_cursor[i] = incl - v + wsum[wid];
}

__global__ void scan_sums_kernel(int nb) {
    int lane = threadIdx.x;
    int va = (lane < nb) ? g_bsum[lane] : 0;
    int vb = (32 + lane < nb) ? g_bsum[32 + lane] : 0;
    int a = va, b = vb;
#pragma unroll
    for (int off = 1; off < 32; off <<= 1) {
        int t = __shfl_up_sync(0xFFFFFFFFu, a, off);
        if (lane >= off) a += t;
        int u = __shfl_up_sync(0xFFFFFFFFu, b, off);
        if (lane >= off) b += u;
    }
    int totA = __shfl_sync(0xFFFFFFFFu, a, 31);
    if (lane < nb) g_bsum[lane] = a - va;
    if (32 + lane < nb) g_bsum[32 + lane] = totA + b - vb;
}

__global__ void scan_add_kernel() {
    int i = blockIdx.x * blockDim.x + threadIdx.x;
    if (i < NN) {
        int r = g_cursor[i] + g_bsum[i >> 10];
        g_rowptr[i] = r;
        g_cursor[i] = r;
    }
    if (i == 0) g_rowptr[NN] = EE;
}

__global__ void scatter_kernel() {
    int i = blockIdx.x * blockDim.x + threadIdx.x;
    if (i >= EE) return;
    int d = g_dst[i];
    int pos = atomicAdd(&g_cursor[d], 1);
    g_colsrc[pos] = g_src[i];
}

// ---------------- tiled GEMM: fp16 feat store + fused el/er epilogue --------
template <int FIN, int HD, int TM, int TX, int TY, int H>
__global__ void gemm_tiled_kernel(const float* __restrict__ x,
                                  const float* __restrict__ W,
                                  const float* __restrict__ al,
                                  const float* __restrict__ ar,
                                  __half* __restrict__ feat,
                                  float* __restrict__ el,
                                  float* __restrict__ er) {
    constexpr int NODES = TM * TY;
    constexpr int D = HD / H;
    extern __shared__ float sh[];
    float* Wsh = sh;                 // [FIN][HD]
    float* Xsh = sh + FIN * HD;      // [NODES][FIN]
    int node0 = blockIdx.x * NODES;
    int tid = threadIdx.x;

    for (int i = tid; i < FIN * HD / 4; i += TX * TY)
        ((float4*)Wsh)[i] = ((const float4*)W)[i];
    for (int i = tid; i < NODES * FIN / 4; i += TX * TY) {
        int n = i / (FIN / 4), k4 = i % (FIN / 4);
        int gn = node0 + n;
        ((float4*)Xsh)[i] = (gn < NN) ? ((const float4*)(x + (size_t)gn * FIN))[k4]
                                      : make_float4(0.f, 0.f, 0.f, 0.f);
    }
    __syncthreads();

    int tx = tid % TX, ty = tid / TX;
    float ac[TM][4];
#pragma unroll
    for (int m = 0; m < TM; m++)
#pragma unroll
        for (int n = 0; n < 4; n++) ac[m][n] = 0.f;

#pragma unroll 4
    for (int k = 0; k < FIN; k++) {
        float4 wv = ((float4*)(Wsh + k * HD))[tx];
#pragma unroll
        for (int m = 0; m < TM; m++) {
            float xv = Xsh[(ty * TM + m) * FIN + k];
            ac[m][0] += xv * wv.x;
            ac[m][1] += xv * wv.y;
            ac[m][2] += xv * wv.z;
            ac[m][3] += xv * wv.w;
        }
    }

    float4 alv = ((const float4*)al)[tx];
    float4 arv = ((const float4*)ar)[tx];
#pragma unroll
    for (int m = 0; m < TM; m++) {
        int node = node0 + ty * TM + m;
        float pl = ac[m][0] * alv.x + ac[m][1] * alv.y + ac[m][2] * alv.z + ac[m][3] * alv.w;
        float pr = ac[m][0] * arv.x + ac[m][1] * arv.y + ac[m][2] * arv.z + ac[m][3] * arv.w;
#pragma unroll
        for (int off = 8; off; off >>= 1) {
            pl += __shfl_xor_sync(0xFFFFFFFFu, pl, off);
            pr += __shfl_xor_sync(0xFFFFFFFFu, pr, off);
        }
        if (node < NN) {
            __half2 p0 = __floats2half2_rn(ac[m][0], ac[m][1]);
            __half2 p1 = __floats2half2_rn(ac[m][2], ac[m][3]);
            *(__half2*)(feat + (size_t)node * HD + 4 * tx)     = p0;
            *(__half2*)(feat + (size_t)node * HD + 4 * tx + 2) = p1;
            if ((tx & 15) == 0) {
                int h = (4 * tx) / D;
                el[node * H + h] = pl;
                er[node * H + h] = pr;
            }
        }
    }
}

// ---------------- small fused GEMM (layer 2 only: Fin=64, HD=40) -------------
__global__ void gemm_feat_kernel(const float* __restrict__ x,
                                 const float* __restrict__ W,
                                 const float* __restrict__ al,
                                 const float* __restrict__ ar,
                                 __half* __restrict__ feat,
                                 float* __restrict__ el,
                                 float* __restrict__ er,
                                 int Fin, int H, int D) {
    int gwarp = (blockIdx.x * blockDim.x + threadIdx.x) >> 5;
    int lane  = threadIdx.x & 31;
    if (gwarp >= NN) return;
    int HD  = H * D;
    int HD4 = HD >> 2;
    bool active = lane < HD4;

    const float* xrow = x + (size_t)gwarp * Fin;
    float xr[4];
#pragma unroll
    for (int w = 0; w < 4; w++) {
        int k = lane + 32 * w;
        xr[w] = (k < Fin) ? xrow[k] : 0.0f;
    }

    float a0 = 0.f, a1 = 0.f, a2 = 0.f, a3 = 0.f;
    const float4* W4 = (const float4*)W;
    for (int w = 0; w < 4; w++) {
        if (32 * w >= Fin) break;
        float xw = xr[w];
#pragma unroll
        for (int kk = 0; kk < 32; kk++) {
            float xk = __shfl_sync(0xFFFFFFFFu, xw, kk);
            if (active) {
                float4 wv = __ldg(&W4[(32 * w + kk) * HD4 + lane]);
                a0 += xk * wv.x; a1 += xk * wv.y;
                a2 += xk * wv.z; a3 += xk * wv.w;
            }
        }
    }

    float pl = 0.f, pr = 0.f;
    if (active) {
        __half2 p0 = __floats2half2_rn(a0, a1);
        __half2 p1 = __floats2half2_rn(a2, a3);
        *(__half2*)(feat + (size_t)gwarp * HD + 4 * lane)     = p0;
        *(__half2*)(feat + (size_t)gwarp * HD + 4 * lane + 2) = p1;
        int c = 4 * lane;
        pl = a0 * al[c] + a1 * al[c + 1] + a2 * al[c + 2] + a3 * al[c + 3];
        pr = a0 * ar[c] + a1 * ar[c + 1] + a2 * ar[c + 2] + a3 * ar[c + 3];
    }
#pragma unroll
    for (int off = 16; off; off >>= 1) {
        pl += __shfl_xor_sync(0xFFFFFFFFu, pl, off);
        pr += __shfl_xor_sync(0xFFFFFFFFu, pr, off);
    }
    if (lane == 0) { el[gwarp] = pl; er[gwarp] = pr; }
}

// ---------------- single-pass fused softmax + aggregation (fp16 gather) -----
// LPN lanes per node, 8 columns per lane (one uint4 = 8 halves per gather).
// exp(v)/sum == softmax (no max shift needed; |v| small). fp32 accumulation.
template <int H, int D, int LPN, int GPW>
__global__ void fused_attn_kernel(const __half* __restrict__ feat,
                                  const float* __restrict__ el,
                                  const float* __restrict__ er,
                                  const float* __restrict__ bias,
                                  float* __restrict__ out) {
    constexpr int HD = H * D;
    static_assert(LPN * 8 == HD, "lanes*8 must equal HD");
    int warp = (blockIdx.x * blockDim.x + threadIdx.x) >> 5;
    int lane = threadIdx.x & 31;
    int g    = lane / LPN;
    int sub  = lane - g * LPN;
    int node = warp * GPW + g;
    if (g >= GPW || node >= NN) return;

    const int h    = (8 * sub) / D;
    const float er_d = __ldg(&er[node * H + h]);
    const int e0 = g_rowptr[node];
    const int e1 = g_rowptr[node + 1];

    float ssum = 0.f;
    float a0 = 0.f, a1 = 0.f, a2 = 0.f, a3 = 0.f;
    float a4 = 0.f, a5 = 0.f, a6 = 0.f, a7 = 0.f;
#pragma unroll 4
    for (int e = e0; e < e1; e++) {
        int s   = __ldg(&g_colsrc[e]);
        float v = __ldg(&el[s * H + h]) + er_d;
        v = v > 0.f ? v : 0.2f * v;
        float p = __expf(v);
        uint4 raw = __ldg((const uint4*)(feat + (size_t)s * HD + 8 * sub));
        float2 f0 = __half22float2(*(const __half2*)&raw.x);
        float2 f1 = __half22float2(*(const __half2*)&raw.y);
        float2 f2 = __half22float2(*(const __half2*)&raw.z);
        float2 f3 = __half22float2(*(const __half2*)&raw.w);
        a0 += p * f0.x; a1 += p * f0.y;
        a2 += p * f1.x; a3 += p * f1.y;
        a4 += p * f2.x; a5 += p * f2.y;
        a6 += p * f3.x; a7 += p * f3.y;
        ssum += p;
    }
    float inv = __frcp_rn(ssum);
    float4 blo = __ldg((const float4*)(bias + 8 * sub));
    float4 bhi = __ldg((const float4*)(bias + 8 * sub + 4));
    float4 o0, o1;
    o0.x = a0 * inv + blo.x; o0.y = a1 * inv + blo.y;
    o0.z = a2 * inv + blo.z; o0.w = a3 * inv + blo.w;
    o1.x = a4 * inv + bhi.x; o1.y = a5 * inv + bhi.y;
    o1.z = a6 * inv + bhi.z; o1.w = a7 * inv + bhi.w;
    float* orow = out + (size_t)node * HD + 8 * sub;
    *(float4*)orow       = o0;
    *(float4*)(orow + 4) = o1;
}

// ---------------- launcher ---------------------------------------------------
extern "C" void kernel_launch(void* const* d_in, const int* in_sizes, int n_in,
                              void* d_out, int out_size) {
    const float* in_feat = (const float*)d_in[0];
    const void*  src     = d_in[1];
    const void*  dst     = d_in[2];
    const float* W0 = (const float*)d_in[3];
    const float* al0 = (const float*)d_in[4];
    const float* ar0 = (const float*)d_in[5];
    const float* b0 = (const float*)d_in[6];
    const float* W1 = (const float*)d_in[7];
    const float* al1 = (const float*)d_in[8];
    const float* ar1 = (const float*)d_in[9];
    const float* b1 = (const float*)d_in[10];
    const float* W2 = (const float*)d_in[11];
    const float* al2 = (const float*)d_in[12];
    const float* ar2 = (const float*)d_in[13];
    const float* b2 = (const float*)d_in[14];
    float* out = (float*)d_out;

    __half* feat_p;
    float *h0_p, *h1_p, *el_p, *er_p;
    int* count_p;
    cudaGetSymbolAddress((void**)&feat_p, g_feat16);
    cudaGetSymbolAddress((void**)&h0_p, g_h0);
    cudaGetSymbolAddress((void**)&h1_p, g_h1);
    cudaGetSymbolAddress((void**)&el_p, g_el);
    cudaGetSymbolAddress((void**)&er_p, g_er);
    cudaGetSymbolAddress((void**)&count_p, g_count);

    constexpr int SMEM_L0 = (128 * 128 + 64 * 128) * 4;  // 96 KB
    constexpr int SMEM_L1 = (128 * 64 + 64 * 128) * 4;   // 64 KB
    cudaFuncSetAttribute(gemm_tiled_kernel<128, 128, 8, 32, 8, 2>,
                         cudaFuncAttributeMaxDynamicSharedMemorySize, SMEM_L0);
    cudaFuncSetAttribute(gemm_tiled_kernel<128, 64, 4, 16, 16, 1>,
                         cudaFuncAttributeMaxDynamicSharedMemorySize, SMEM_L1);

    // ---- try to insert GEMM0 as a root graph node (runs parallel to CSR) ----
    bool manual = false;
    cudaGraphNode_t gemm0_node;
    {
        cudaStreamCaptureStatus st = cudaStreamCaptureStatusNone;
        cudaGraph_t cgraph = nullptr;
        const cudaGraphNode_t* cdeps = nullptr;
        const cudaGraphEdgeData* cedges = nullptr;
        size_t nd = 0;
        unsigned long long cid = 0;
        if (cudaStreamGetCaptureInfo((cudaStream_t)0, &st, &cid, &cgraph,
                                     &cdeps, &cedges, &nd) == cudaSuccess &&
            st == cudaStreamCaptureStatusActive && cgraph != nullptr) {
            cudaKernelNodeParams p = {};
            const float* a_in = in_feat;
            const float* a_W = W0;
            const float* a_al = al0;
            const float* a_ar = ar0;
            __half* a_feat = feat_p;
            float* a_el = el_p;
            float* a_er = er_p;
            void* args[7] = {&a_in, &a_W, &a_al, &a_ar, &a_feat, &a_el, &a_er};
            p.func = (void*)gemm_tiled_kernel<128, 128, 8, 32, 8, 2>;
            p.gridDim = dim3((NN + 63) / 64, 1, 1);
            p.blockDim = dim3(256, 1, 1);
            p.sharedMemBytes = SMEM_L0;
            p.kernelParams = args;
            p.extra = nullptr;
            if (cudaGraphAddKernelNode(&gemm0_node, cgraph, nullptr, 0, &p)
                    == cudaSuccess)
                manual = true;
        }
    }

    // ---- CSR build chain (in-stream; overlaps with GEMM0) ----
    detect_kernel<<<1, 1>>>((const unsigned*)src, (const unsigned*)dst);
    cudaMemsetAsync(count_p, 0, NN * sizeof(int));
    hist_kernel<<<(EE + 255) / 256, 256>>>(src, dst);
    int nb = (NN + 1023) / 1024;
    scan_block_kernel<<<nb, 1024>>>();
    scan_sums_kernel<<<1, 32>>>(nb);
    scan_add_kernel<<<(NN + 255) / 256, 256>>>();
    scatter_kernel<<<(EE + 255) / 256, 256>>>();

    // ---- join GEMM0 into the stream (or launch it here if not capturing) ----
    if (manual) {
        cudaStreamUpdateCaptureDependencies((cudaStream_t)0, &gemm0_node,
                                            nullptr, 1,
                                            cudaStreamAddCaptureDependencies);
    } else {
        gemm_tiled_kernel<128, 128, 8, 32, 8, 2>
            <<<(NN + 63) / 64, 256, SMEM_L0>>>(in_feat, W0, al0, ar0,
                                               feat_p, el_p, er_p);
    }

    // ---- layer 0 edge phase: 16 lanes/node, 2 nodes/warp ----
    {
        int warps = (NN + 1) / 2;
        fused_attn_kernel<2, 64, 16, 2>
            <<<(warps * 32 + 255) / 256, 256>>>(feat_p, el_p, er_p, b0, h0_p);
    }

    // ---- layer 1: 128 -> 1 head x 64 ----
    gemm_tiled_kernel<128, 64, 4, 16, 16, 1>
        <<<(NN + 63) / 64, 256, SMEM_L1>>>(h0_p, W1, al1, ar1, feat_p, el_p, er_p);
    {
        int warps = (NN + 3) / 4;
        fused_attn_kernel<1, 64, 8, 4>
            <<<(warps * 32 + 255) / 256, 256>>>(feat_p, el_p, er_p, b1, h1_p);
    }

    // ---- layer 2: 64 -> 1 head x 40 -> d_out ----
    gemm_feat_kernel<<<(NN + 7) / 8, 256>>>(h1_p, W2, al2, ar2, feat_p, el_p, er_p, 64, 1, 40);
    {
        int warps = (NN + 5) / 6;
        fused_attn_kernel<1, 40, 5, 6>
            <<<(warps * 32 + 255) / 256, 256>>>(feat_p, el_p, er_p, b2, out);
    }
}

// round 9
// speedup vs baseline: 1.3697x; 1.3697x over previous
#include <cuda_runtime.h>
#include <math_constants.h>

#define NN 50000
#define EE 850000
#define SPLIT 25024   // node split point (multiple of 64 and of 2)

// ---------------- scratch (device globals; no allocation allowed) ----------
__device__ float g_featA[NN * 128];  // layer0 transformed features
__device__ float g_featB[NN * 64];   // layer1
__device__ float g_featC[NN * 40];   // layer2
__device__ float g_h0[NN * 128];
__device__ float g_h1[NN * 64];
__device__ float g_elA[NN * 2], g_erA[NN * 2];
__device__ float g_elB[NN],     g_erB[NN];
__device__ float g_elC[NN],     g_erC[NN];
__device__ int   g_src[EE];
__device__ int   g_dst[EE];
__device__ int   g_count[NN];
__device__ int   g_cursor[NN];
__device__ int   g_rowptr[NN + 1];
__device__ int   g_colsrc[EE];
__device__ int   g_bsum[64];
__device__ int   g_is64;

// ---------------- index width detection ------------------------------------
__global__ void detect_kernel(const unsigned* src_w, const unsigned* dst_w) {
    int i64 = 1;
    for (int k = 0; k < 16; k++) {
        if (src_w[2 * k + 1] != 0u) i64 = 0;
        if (dst_w[2 * k + 1] != 0u) i64 = 0;
    }
    g_is64 = i64;
}

__global__ void hist_kernel(const void* src, const void* dst) {
    int i = blockIdx.x * blockDim.x + threadIdx.x;
    if (i >= EE) return;
    int s, d;
    if (g_is64) {
        s = (int)((const long long*)src)[i];
        d = (int)((const long long*)dst)[i];
    } else {
        s = ((const int*)src)[i];
        d = ((const int*)dst)[i];
    }
    g_src[i] = s;
    g_dst[i] = d;
    atomicAdd(&g_count[d], 1);
}

// ---------------- 2-phase exclusive scan ------------------------------------
__global__ void scan_block_kernel() {
    __shared__ int wsum[32];
    int i = blockIdx.x * 1024 + threadIdx.x;
    int lane = threadIdx.x & 31, wid = threadIdx.x >> 5;
    int v = (i < NN) ? g_count[i] : 0;
    int incl = v;
#pragma unroll
    for (int off = 1; off < 32; off <<= 1) {
        int t = __shfl_up_sync(0xFFFFFFFFu, incl, off);
        if (lane >= off) incl += t;
    }
    if (lane == 31) wsum[wid] = incl;
    __syncthreads();
    if (wid == 0) {
        int s = wsum[lane];
        int si = s;
#pragma unroll
        for (int off = 1; off < 32; off <<= 1) {
            int t = __shfl_up_sync(0xFFFFFFFFu, si, off);
            if (lane >= off) si += t;
        }
        wsum[lane] = si - s;
        if (lane == 31) g_bsum[blockIdx.x] = si;
    }
    __syncthreads();
    if (i < NN) g_cursor[i] = incl - v + wsum[wid];
}

// merged: every block redundantly scans the <=49 block sums, then applies.
__global__ void scan_add_kernel(int nb) {
    __shared__ int soff[64];
    if (threadIdx.x == 0) {
        int acc = 0;
        for (int j = 0; j < nb; j++) { soff[j] = acc; acc += g_bsum[j]; }
    }
    __syncthreads();
    int i = blockIdx.x * blockDim.x + threadIdx.x;
    if (i < NN) {
        int r = g_cursor[i] + soff[i >> 10];
        g_rowptr[i] = r;
        g_cursor[i] = r;
    }
    if (i == 0) g_rowptr[NN] = EE;
}

__global__ void scatter_kernel() {
    int i = blockIdx.x * blockDim.x + threadIdx.x;
    if (i >= EE) return;
    int d = g_dst[i];
    int pos = atomicAdd(&g_cursor[d], 1);
    g_colsrc[pos] = g_src[i];
}

// ---------------- tiled GEMM with fused el/er epilogue (node_base aware) -----
template <int FIN, int HD, int TM, int TX, int TY, int H>
__global__ void gemm_tiled_kernel(const float* __restrict__ x,
                                  const float* __restrict__ W,
                                  const float* __restrict__ al,
                                  const float* __restrict__ ar,
                                  float* __restrict__ feat,
                                  float* __restrict__ el,
                                  float* __restrict__ er,
                                  int node_base) {
    constexpr int NODES = TM * TY;
    constexpr int D = HD / H;
    extern __shared__ float sh[];
    float* Wsh = sh;                 // [FIN][HD]
    float* Xsh = sh + FIN * HD;      // [NODES][FIN]
    int node0 = node_base + blockIdx.x * NODES;
    int tid = threadIdx.x;

    for (int i = tid; i < FIN * HD / 4; i += TX * TY)
        ((float4*)Wsh)[i] = ((const float4*)W)[i];
    for (int i = tid; i < NODES * FIN / 4; i += TX * TY) {
        int n = i / (FIN / 4), k4 = i % (FIN / 4);
        int gn = node0 + n;
        ((float4*)Xsh)[i] = (gn < NN) ? ((const float4*)(x + (size_t)gn * FIN))[k4]
                                      : make_float4(0.f, 0.f, 0.f, 0.f);
    }
    __syncthreads();

    int tx = tid % TX, ty = tid / TX;
    float ac[TM][4];
#pragma unroll
    for (int m = 0; m < TM; m++)
#pragma unroll
        for (int n = 0; n < 4; n++) ac[m][n] = 0.f;

#pragma unroll 4
    for (int k = 0; k < FIN; k++) {
        float4 wv = ((float4*)(Wsh + k * HD))[tx];
#pragma unroll
        for (int m = 0; m < TM; m++) {
            float xv = Xsh[(ty * TM + m) * FIN + k];
            ac[m][0] += xv * wv.x;
            ac[m][1] += xv * wv.y;
            ac[m][2] += xv * wv.z;
            ac[m][3] += xv * wv.w;
        }
    }

    float4 alv = ((const float4*)al)[tx];
    float4 arv = ((const float4*)ar)[tx];
#pragma unroll
    for (int m = 0; m < TM; m++) {
        int node = node0 + ty * TM + m;
        float pl = ac[m][0] * alv.x + ac[m][1] * alv.y + ac[m][2] * alv.z + ac[m][3] * alv.w;
        float pr = ac[m][0] * arv.x + ac[m][1] * arv.y + ac[m][2] * arv.z + ac[m][3] * arv.w;
#pragma unroll
        for (int off = 8; off; off >>= 1) {
            pl += __shfl_xor_sync(0xFFFFFFFFu, pl, off);
            pr += __shfl_xor_sync(0xFFFFFFFFu, pr, off);
        }
        if (node < NN) {
            ((float4*)(feat + (size_t)node * HD))[tx] =
                make_float4(ac[m][0], ac[m][1], ac[m][2], ac[m][3]);
            if ((tx & 15) == 0) {
                int h = (4 * tx) / D;
                el[node * H + h] = pl;
                er[node * H + h] = pr;
            }
        }
    }
}

// ---------------- small fused GEMM (layer 2: Fin=64, HD=40), range aware -----
__global__ void gemm_feat_kernel(const float* __restrict__ x,
                                 const float* __restrict__ W,
                                 const float* __restrict__ al,
                                 const float* __restrict__ ar,
                                 float* __restrict__ feat,
                                 float* __restrict__ el,
                                 float* __restrict__ er,
                                 int Fin, int H, int D, int base, int count) {
    int gwarp = base + ((blockIdx.x * blockDim.x + threadIdx.x) >> 5);
    int lane  = threadIdx.x & 31;
    if (gwarp >= base + count || gwarp >= NN) return;
    int HD  = H * D;
    int HD4 = HD >> 2;
    bool active = lane < HD4;

    const float* xrow = x + (size_t)gwarp * Fin;
    float xr[4];
#pragma unroll
    for (int w = 0; w < 4; w++) {
        int k = lane + 32 * w;
        xr[w] = (k < Fin) ? xrow[k] : 0.0f;
    }

    float a0 = 0.f, a1 = 0.f, a2 = 0.f, a3 = 0.f;
    const float4* W4 = (const float4*)W;
    for (int w = 0; w < 4; w++) {
        if (32 * w >= Fin) break;
        float xw = xr[w];
#pragma unroll
        for (int kk = 0; kk < 32; kk++) {
            float xk = __shfl_sync(0xFFFFFFFFu, xw, kk);
            if (active) {
                float4 wv = __ldg(&W4[(32 * w + kk) * HD4 + lane]);
                a0 += xk * wv.x; a1 += xk * wv.y;
                a2 += xk * wv.z; a3 += xk * wv.w;
            }
        }
    }

    float pl = 0.f, pr = 0.f;
    if (active) {
        ((float4*)(feat + (size_t)gwarp * HD))[lane] = make_float4(a0, a1, a2, a3);
        int c = 4 * lane;
        pl = a0 * al[c] + a1 * al[c + 1] + a2 * al[c + 2] + a3 * al[c + 3];
        pr = a0 * ar[c] + a1 * ar[c + 1] + a2 * ar[c + 2] + a3 * ar[c + 3];
    }
#pragma unroll
    for (int off = 16; off; off >>= 1) {
        pl += __shfl_xor_sync(0xFFFFFFFFu, pl, off);
        pr += __shfl_xor_sync(0xFFFFFFFFu, pr, off);
    }
    if (lane == 0) { el[gwarp] = pl; er[gwarp] = pr; }
}

// ---------------- single-pass fused softmax + aggregation (fp32, R7 form) ---
template <int H, int D, int GPW>
__global__ void fused_attn_kernel(const float* __restrict__ feat,
                                  const float* __restrict__ el,
                                  const float* __restrict__ er,
                                  const float* __restrict__ bias,
                                  float* __restrict__ out,
                                  int base, int count) {
    constexpr int HD  = H * D;
    constexpr int HD4 = HD / 4;
    int warp = (blockIdx.x * blockDim.x + threadIdx.x) >> 5;
    int lane = threadIdx.x & 31;
    int g    = lane / HD4;
    int sub  = lane - g * HD4;
    int node = base + warp * GPW + g;
    if (g >= GPW || node >= base + count || node >= NN) return;

    const int h    = (4 * sub) / D;
    const float er_d = __ldg(&er[node * H + h]);
    const int e0 = g_rowptr[node];
    const int e1 = g_rowptr[node + 1];

    float ssum = 0.f;
    float ax = 0.f, ay = 0.f, az = 0.f, aw = 0.f;
#pragma unroll 4
    for (int e = e0; e < e1; e++) {
        int s   = __ldg(&g_colsrc[e]);
        float v = __ldg(&el[s * H + h]) + er_d;
        v = v > 0.f ? v : 0.2f * v;
        float p = __expf(v);
        float4 f = __ldg((const float4*)(feat + (size_t)s * HD + 4 * sub));
        ax += p * f.x;
        ay += p * f.y;
        az += p * f.z;
        aw += p * f.w;
        ssum += p;
    }
    float inv = __frcp_rn(ssum);
    float4 o;
    o.x = ax * inv + __ldg(&bias[4 * sub + 0]);
    o.y = ay * inv + __ldg(&bias[4 * sub + 1]);
    o.z = az * inv + __ldg(&bias[4 * sub + 2]);
    o.w = aw * inv + __ldg(&bias[4 * sub + 3]);
    *(float4*)(out + (size_t)node * HD + 4 * sub) = o;
}

// ---------------- graph-node helper ------------------------------------------
static bool add_knode(cudaGraph_t g, cudaGraphNode_t* out,
                      const cudaGraphNode_t* deps, size_t nd,
                      void* func, dim3 grid, dim3 block, unsigned smem,
                      void** args) {
    cudaKernelNodeParams p = {};
    p.func = func;
    p.gridDim = grid;
    p.blockDim = block;
    p.sharedMemBytes = smem;
    p.kernelParams = args;
    p.extra = nullptr;
    return cudaGraphAddKernelNode(out, g, deps, nd, &p) == cudaSuccess;
}

// ---------------- launcher ---------------------------------------------------
extern "C" void kernel_launch(void* const* d_in, const int* in_sizes, int n_in,
                              void* d_out, int out_size) {
    const float* in_feat = (const float*)d_in[0];
    const void*  src     = d_in[1];
    const void*  dst     = d_in[2];
    const float* W0 = (const float*)d_in[3];
    const float* al0 = (const float*)d_in[4];
    const float* ar0 = (const float*)d_in[5];
    const float* b0 = (const float*)d_in[6];
    const float* W1 = (const float*)d_in[7];
    const float* al1 = (const float*)d_in[8];
    const float* ar1 = (const float*)d_in[9];
    const float* b1 = (const float*)d_in[10];
    const float* W2 = (const float*)d_in[11];
    const float* al2 = (const float*)d_in[12];
    const float* ar2 = (const float*)d_in[13];
    const float* b2 = (const float*)d_in[14];
    float* out = (float*)d_out;

    float *featA, *featB, *featC, *h0_p, *h1_p;
    float *elA, *erA, *elB, *erB, *elC, *erC;
    int* count_p;
    cudaGetSymbolAddress((void**)&featA, g_featA);
    cudaGetSymbolAddress((void**)&featB, g_featB);
    cudaGetSymbolAddress((void**)&featC, g_featC);
    cudaGetSymbolAddress((void**)&h0_p, g_h0);
    cudaGetSymbolAddress((void**)&h1_p, g_h1);
    cudaGetSymbolAddress((void**)&elA, g_elA);
    cudaGetSymbolAddress((void**)&erA, g_erA);
    cudaGetSymbolAddress((void**)&elB, g_elB);
    cudaGetSymbolAddress((void**)&erB, g_erB);
    cudaGetSymbolAddress((void**)&elC, g_elC);
    cudaGetSymbolAddress((void**)&erC, g_erC);
    cudaGetSymbolAddress((void**)&count_p, g_count);

    constexpr int SMEM_L0 = (128 * 128 + 64 * 128) * 4;  // 96 KB
    constexpr int SMEM_L1 = (128 * 64 + 64 * 128) * 4;   // 64 KB
    cudaFuncSetAttribute(gemm_tiled_kernel<128, 128, 8, 32, 8, 2>,
                         cudaFuncAttributeMaxDynamicSharedMemorySize, SMEM_L0);
    cudaFuncSetAttribute(gemm_tiled_kernel<128, 64, 4, 16, 16, 1>,
                         cudaFuncAttributeMaxDynamicSharedMemorySize, SMEM_L1);

    const int nb = (NN + 1023) / 1024;
    const int CNT_B = NN - SPLIT;
    // grids
    const dim3 blk256(256, 1, 1);
    const dim3 grid_gemm0((NN + 63) / 64, 1, 1);
    const dim3 grid_attn0A((SPLIT * 32 + 255) / 256, 1, 1);
    const dim3 grid_attn0B((CNT_B * 32 + 255) / 256, 1, 1);
    const dim3 grid_gemm1half(SPLIT / 64, 1, 1);          // 391 (covers SPLIT exactly)
    const dim3 grid_gemm1B((CNT_B + 63) / 64, 1, 1);
    const dim3 grid_attn1A((SPLIT / 2 * 32 + 255) / 256, 1, 1);
    const dim3 grid_attn1B(((CNT_B + 1) / 2 * 32 + 255) / 256, 1, 1);
    const dim3 grid_gemm2A((SPLIT + 7) / 8, 1, 1);
    const dim3 grid_gemm2B((CNT_B + 7) / 8, 1, 1);
    const dim3 grid_attn2(((NN + 2) / 3 * 32 + 255) / 256, 1, 1);

    // ---- capture state ----
    cudaStreamCaptureStatus st = cudaStreamCaptureStatusNone;
    cudaGraph_t graph = nullptr;
    const cudaGraphNode_t* deps = nullptr;
    const cudaGraphEdgeData* edges = nullptr;
    size_t nd = 0;
    unsigned long long cid = 0;
    bool capturing =
        (cudaStreamGetCaptureInfo((cudaStream_t)0, &st, &cid, &graph,
                                  &deps, &edges, &nd) == cudaSuccess) &&
        st == cudaStreamCaptureStatusActive && graph != nullptr;

    // ---- GEMM0 as root node (overlaps the CSR chain) ----
    bool overlap = false;
    cudaGraphNode_t n_gemm0;
    if (capturing) {
        const float* ax = in_feat; const float* aW = W0;
        const float* aal = al0; const float* aar = ar0;
        float* af = featA; float* ael = elA; float* aer = erA; int ab = 0;
        void* args[8] = {&ax, &aW, &aal, &aar, &af, &ael, &aer, &ab};
        overlap = add_knode(graph, &n_gemm0, nullptr, 0,
                            (void*)gemm_tiled_kernel<128, 128, 8, 32, 8, 2>,
                            grid_gemm0, blk256, SMEM_L0, args);
    }

    // ---- CSR build chain (in-stream) ----
    detect_kernel<<<1, 1>>>((const unsigned*)src, (const unsigned*)dst);
    cudaMemsetAsync(count_p, 0, NN * sizeof(int));
    hist_kernel<<<(EE + 255) / 256, 256>>>(src, dst);
    scan_block_kernel<<<nb, 1024>>>();
    scan_add_kernel<<<(NN + 255) / 256, 256>>>(nb);
    scatter_kernel<<<(EE + 255) / 256, 256>>>();

    if (!overlap) {
        // ---------- sequential fallback (correctness run / no capture) ----------
        gemm_tiled_kernel<128, 128, 8, 32, 8, 2>
            <<<grid_gemm0, blk256, SMEM_L0>>>(in_feat, W0, al0, ar0, featA, elA, erA, 0);
        fused_attn_kernel<2, 64, 1><<<grid_attn0A, blk256>>>(featA, elA, erA, b0, h0_p, 0, SPLIT);
        fused_attn_kernel<2, 64, 1><<<grid_attn0B, blk256>>>(featA, elA, erA, b0, h0_p, SPLIT, CNT_B);
        gemm_tiled_kernel<128, 64, 4, 16, 16, 1>
            <<<grid_gemm1half, blk256, SMEM_L1>>>(h0_p, W1, al1, ar1, featB, elB, erB, 0);
        gemm_tiled_kernel<128, 64, 4, 16, 16, 1>
            <<<grid_gemm1B, blk256, SMEM_L1>>>(h0_p, W1, al1, ar1, featB, elB, erB, SPLIT);
        fused_attn_kernel<1, 64, 2><<<grid_attn1A, blk256>>>(featB, elB, erB, b1, h1_p, 0, SPLIT);
        fused_attn_kernel<1, 64, 2><<<grid_attn1B, blk256>>>(featB, elB, erB, b1, h1_p, SPLIT, CNT_B);
        gemm_feat_kernel<<<grid_gemm2A, blk256>>>(h1_p, W2, al2, ar2, featC, elC, erC, 64, 1, 40, 0, SPLIT);
        gemm_feat_kernel<<<grid_gemm2B, blk256>>>(h1_p, W2, al2, ar2, featC, elC, erC, 64, 1, 40, SPLIT, CNT_B);
        fused_attn_kernel<1, 40, 3><<<grid_attn2, blk256>>>(featC, elC, erC, b2, out, 0, NN);
        return;
    }

    // ---------- overlapped graph path ----------
    // join gemm0 into the frontier (frontier = {scatter, gemm0})
    cudaStreamUpdateCaptureDependencies((cudaStream_t)0, &n_gemm0, nullptr, 1,
                                        cudaStreamAddCaptureDependencies);

    // snapshot frontier F0 (deps for attn0B)
    cudaGraphNode_t F0[16]; size_t nF0 = 0;
    if (cudaStreamGetCaptureInfo((cudaStream_t)0, &st, &cid, &graph,
                                 &deps, &edges, &nd) == cudaSuccess) {
        nF0 = nd > 16 ? 16 : nd;
        for (size_t i = 0; i < nF0; i++) F0[i] = deps[i];
    }

    // attn0A in-stream
    fused_attn_kernel<2, 64, 1><<<grid_attn0A, blk256>>>(featA, elA, erA, b0, h0_p, 0, SPLIT);

    // attn0B as manual node depending on F0 (parallel to gemm1A)
    bool b0ok = false;
    cudaGraphNode_t n_attn0B;
    {
        const float* af = featA; const float* ael = elA; const float* aer = erA;
        const float* ab = b0; float* ao = h0_p; int abase = SPLIT; int acnt = CNT_B;
        void* args[7] = {&af, &ael, &aer, &ab, &ao, &abase, &acnt};
        b0ok = add_knode(graph, &n_attn0B, F0, nF0,
                         (void*)fused_attn_kernel<2, 64, 1>,
                         grid_attn0B, blk256, 0, args);
    }
    if (!b0ok)
        fused_attn_kernel<2, 64, 1><<<grid_attn0B, blk256>>>(featA, elA, erA, b0, h0_p, SPLIT, CNT_B);

    // gemm1A in-stream (deps: attn0A)
    gemm_tiled_kernel<128, 64, 4, 16, 16, 1>
        <<<grid_gemm1half, blk256, SMEM_L1>>>(h0_p, W1, al1, ar1, featB, elB, erB, 0);
    if (b0ok)
        cudaStreamUpdateCaptureDependencies((cudaStream_t)0, &n_attn0B, nullptr, 1,
                                            cudaStreamAddCaptureDependencies);
    // gemm1B in-stream (deps: gemm1A + attn0B)
    gemm_tiled_kernel<128, 64, 4, 16, 16, 1>
        <<<grid_gemm1B, blk256, SMEM_L1>>>(h0_p, W1, al1, ar1, featB, elB, erB, SPLIT);

    // snapshot frontier F1 (deps for attn1B) = {gemm1B}
    cudaGraphNode_t F1[16]; size_t nF1 = 0;
    if (cudaStreamGetCaptureInfo((cudaStream_t)0, &st, &cid, &graph,
                                 &deps, &edges, &nd) == cudaSuccess) {
        nF1 = nd > 16 ? 16 : nd;
        for (size_t i = 0; i < nF1; i++) F1[i] = deps[i];
    }

    // attn1A in-stream
    fused_attn_kernel<1, 64, 2><<<grid_attn1A, blk256>>>(featB, elB, erB, b1, h1_p, 0, SPLIT);

    // attn1B manual node (parallel to gemm2A)
    bool b1ok = false;
    cudaGraphNode_t n_attn1B;
    {
        const float* af = featB; const float* ael = elB; const float* aer = erB;
        const float* ab = b1; float* ao = h1_p; int abase = SPLIT; int acnt = CNT_B;
        void* args[7] = {&af, &ael, &aer, &ab, &ao, &abase, &acnt};
        b1ok = add_knode(graph, &n_attn1B, F1, nF1,
                         (void*)fused_attn_kernel<1, 64, 2>,
                         grid_attn1B, blk256, 0, args);
    }
    if (!b1ok)
        fused_attn_kernel<1, 64, 2><<<grid_attn1B, blk256>>>(featB, elB, erB, b1, h1_p, SPLIT, CNT_B);

    // gemm2A in-stream (deps: attn1A)
    gemm_feat_kernel<<<grid_gemm2A, blk256>>>(h1_p, W2, al2, ar2, featC, elC, erC, 64, 1, 40, 0, SPLIT);
    if (b1ok)
        cudaStreamUpdateCaptureDependencies((cudaStream_t)0, &n_attn1B, nullptr, 1,
                                            cudaStreamAddCaptureDependencies);
    // gemm2B in-stream (deps: gemm2A + attn1B)
    gemm_feat_kernel<<<grid_gemm2B, blk256>>>(h1_p, W2, al2, ar2, featC, elC, erC, 64, 1, 40, SPLIT, CNT_B);

    // final attn -> d_out
    fused_attn_kernel<1, 40, 3><<<grid_attn2, blk256>>>(featC, elC, erC, b2, out, 0, NN);
}

// round 11
// speedup vs baseline: 1.4881x; 1.0865x over previous
#include <cuda_runtime.h>
#include <cuda_fp16.h>
#include <math_constants.h>

#define NN 50000
#define EE 850000

// ---------------- scratch (device globals; no allocation allowed) ----------
__device__ __half g_feat16[NN * 128];
__device__ float  g_h0[NN * 128];
__device__ float  g_h1[NN * 64];
__device__ float  g_el[NN * 2];
__device__ float  g_er[NN * 2];
__device__ int    g_src[EE];
__device__ int    g_dst[EE];
__device__ int    g_count[NN];
__device__ int    g_cursor[NN];
__device__ int    g_rowptr[NN + 1];
__device__ int    g_colsrc[EE];
__device__ int    g_bsum[64];
__device__ int    g_is64;

// ---------------- index width detection ------------------------------------
__global__ void detect_kernel(const unsigned* src_w, const unsigned* dst_w) {
    int i64 = 1;
    for (int k = 0; k < 16; k++) {
        if (src_w[2 * k + 1] != 0u) i64 = 0;
        if (dst_w[2 * k + 1] != 0u) i64 = 0;
    }
    g_is64 = i64;
}

__global__ void hist_kernel(const void* src, const void* dst) {
    int i = blockIdx.x * blockDim.x + threadIdx.x;
    if (i >= EE) return;
    int s, d;
    if (g_is64) {
        s = (int)((const long long*)src)[i];
        d = (int)((const long long*)dst)[i];
    } else {
        s = ((const int*)src)[i];
        d = ((const int*)dst)[i];
    }
    g_src[i] = s;
    g_dst[i] = d;
    atomicAdd(&g_count[d], 1);
}

// ---------------- 2-phase exclusive scan ------------------------------------
__global__ void scan_block_kernel() {
    __shared__ int wsum[32];
    int i = blockIdx.x * 1024 + threadIdx.x;
    int lane = threadIdx.x & 31, wid = threadIdx.x >> 5;
    int v = (i < NN) ? g_count[i] : 0;
    int incl = v;
#pragma unroll
    for (int off = 1; off < 32; off <<= 1) {
        int t = __shfl_up_sync(0xFFFFFFFFu, incl, off);
        if (lane >= off) incl += t;
    }
    if (lane == 31) wsum[wid] = incl;
    __syncthreads();
    if (wid == 0) {
        int s = wsum[lane];
        int si = s;
#pragma unroll
        for (int off = 1; off < 32; off <<= 1) {
            int t = __shfl_up_sync(0xFFFFFFFFu, si, off);
            if (lane >= off) si += t;
        }
        wsum[lane] = si - s;
        if (lane == 31) g_bsum[blockIdx.x] = si;
    }
    __syncthreads();
    if (i < NN) g_cursor[i] = incl - v + wsum[wid];
}

// merged: every block redundantly scans the <=49 block sums, then applies.
__global__ void scan_add_kernel(int nb) {
    __shared__ int soff[64];
    if (threadIdx.x == 0) {
        int acc = 0;
        for (int j = 0; j < nb; j++) { soff[j] = acc; acc += g_bsum[j]; }
    }
    __syncthreads();
    int i = blockIdx.x * blockDim.x + threadIdx.x;
    if (i < NN) {
        int r = g_cursor[i] + soff[i >> 10];
        g_rowptr[i] = r;
        g_cursor[i] = r;
    }
    if (i == 0) g_rowptr[NN] = EE;
}

__global__ void scatter_kernel() {
    int i = blockIdx.x * blockDim.x + threadIdx.x;
    if (i >= EE) return;
    int d = g_dst[i];
    int pos = atomicAdd(&g_cursor[d], 1);
    g_colsrc[pos] = g_src[i];
}

// ---------------- tiled GEMM: fp16 feat store + fused el/er epilogue --------
template <int FIN, int HD, int TM, int TX, int TY, int H>
__global__ void gemm_tiled_kernel(const float* __restrict__ x,
                                  const float* __restrict__ W,
                                  const float* __restrict__ al,
                                  const float* __restrict__ ar,
                                  __half* __restrict__ feat,
                                  float* __restrict__ el,
                                  float* __restrict__ er) {
    constexpr int NODES = TM * TY;
    constexpr int D = HD / H;
    extern __shared__ float sh[];
    float* Wsh = sh;                 // [FIN][HD]
    float* Xsh = sh + FIN * HD;      // [NODES][FIN]
    int node0 = blockIdx.x * NODES;
    int tid = threadIdx.x;

    for (int i = tid; i < FIN * HD / 4; i += TX * TY)
        ((float4*)Wsh)[i] = ((const float4*)W)[i];
    for (int i = tid; i < NODES * FIN / 4; i += TX * TY) {
        int n = i / (FIN / 4), k4 = i % (FIN / 4);
        int gn = node0 + n;
        ((float4*)Xsh)[i] = (gn < NN) ? ((const float4*)(x + (size_t)gn * FIN))[k4]
                                      : make_float4(0.f, 0.f, 0.f, 0.f);
    }
    __syncthreads();

    int tx = tid % TX, ty = tid / TX;
    float ac[TM][4];
#pragma unroll
    for (int m = 0; m < TM; m++)
#pragma unroll
        for (int n = 0; n < 4; n++) ac[m][n] = 0.f;

#pragma unroll 4
    for (int k = 0; k < FIN; k++) {
        float4 wv = ((float4*)(Wsh + k * HD))[tx];
#pragma unroll
        for (int m = 0; m < TM; m++) {
            float xv = Xsh[(ty * TM + m) * FIN + k];
            ac[m][0] += xv * wv.x;
            ac[m][1] += xv * wv.y;
            ac[m][2] += xv * wv.z;
            ac[m][3] += xv * wv.w;
        }
    }

    float4 alv = ((const float4*)al)[tx];
    float4 arv = ((const float4*)ar)[tx];
#pragma unroll
    for (int m = 0; m < TM; m++) {
        int node = node0 + ty * TM + m;
        float pl = ac[m][0] * alv.x + ac[m][1] * alv.y + ac[m][2] * alv.z + ac[m][3] * alv.w;
        float pr = ac[m][0] * arv.x + ac[m][1] * arv.y + ac[m][2] * arv.z + ac[m][3] * arv.w;
#pragma unroll
        for (int off = 8; off; off >>= 1) {
            pl += __shfl_xor_sync(0xFFFFFFFFu, pl, off);
            pr += __shfl_xor_sync(0xFFFFFFFFu, pr, off);
        }
        if (node < NN) {
            __half2 p0 = __floats2half2_rn(ac[m][0], ac[m][1]);
            __half2 p1 = __floats2half2_rn(ac[m][2], ac[m][3]);
            *(__half2*)(feat + (size_t)node * HD + 4 * tx)     = p0;
            *(__half2*)(feat + (size_t)node * HD + 4 * tx + 2) = p1;
            if ((tx & 15) == 0) {
                int h = (4 * tx) / D;
                el[node * H + h] = pl;
                er[node * H + h] = pr;
            }
        }
    }
}

// ---------------- small fused GEMM (layer 2 only: Fin=64, HD=40) -------------
__global__ void gemm_feat_kernel(const float* __restrict__ x,
                                 const float* __restrict__ W,
                                 const float* __restrict__ al,
                                 const float* __restrict__ ar,
                                 __half* __restrict__ feat,
                                 float* __restrict__ el,
                                 float* __restrict__ er,
                                 int Fin, int H, int D) {
    int gwarp = (blockIdx.x * blockDim.x + threadIdx.x) >> 5;
    int lane  = threadIdx.x & 31;
    if (gwarp >= NN) return;
    int HD  = H * D;
    int HD4 = HD >> 2;
    bool active = lane < HD4;

    const float* xrow = x + (size_t)gwarp * Fin;
    float xr[4];
#pragma unroll
    for (int w = 0; w < 4; w++) {
        int k = lane + 32 * w;
        xr[w] = (k < Fin) ? xrow[k] : 0.0f;
    }

    float a0 = 0.f, a1 = 0.f, a2 = 0.f, a3 = 0.f;
    const float4* W4 = (const float4*)W;
    for (int w = 0; w < 4; w++) {
        if (32 * w >= Fin) break;
        float xw = xr[w];
#pragma unroll
        for (int kk = 0; kk < 32; kk++) {
            float xk = __shfl_sync(0xFFFFFFFFu, xw, kk);
            if (active) {
                float4 wv = __ldg(&W4[(32 * w + kk) * HD4 + lane]);
                a0 += xk * wv.x; a1 += xk * wv.y;
                a2 += xk * wv.z; a3 += xk * wv.w;
            }
        }
    }

    float pl = 0.f, pr = 0.f;
    if (active) {
        __half2 p0 = __floats2half2_rn(a0, a1);
        __half2 p1 = __floats2half2_rn(a2, a3);
        *(__half2*)(feat + (size_t)gwarp * HD + 4 * lane)     = p0;
        *(__half2*)(feat + (size_t)gwarp * HD + 4 * lane + 2) = p1;
        int c = 4 * lane;
        pl = a0 * al[c] + a1 * al[c + 1] + a2 * al[c + 2] + a3 * al[c + 3];
        pr = a0 * ar[c] + a1 * ar[c + 1] + a2 * ar[c + 2] + a3 * ar[c + 3];
    }
#pragma unroll
    for (int off = 16; off; off >>= 1) {
        pl += __shfl_xor_sync(0xFFFFFFFFu, pl, off);
        pr += __shfl_xor_sync(0xFFFFFFFFu, pr, off);
    }
    if (lane == 0) { el[gwarp] = pl; er[gwarp] = pr; }
}

// ---------------- single-pass fused softmax + aggregation (fp16 gather) -----
// EXACT R7 lane geometry: HD/4 lanes per node, 4 columns per lane, GPW as R7.
// Only the feat load narrows: uint2 (4 halves) instead of float4.
template <int H, int D, int GPW>
__global__ void fused_attn_kernel(const __half* __restrict__ feat,
                                  const float* __restrict__ el,
                                  const float* __restrict__ er,
                                  const float* __restrict__ bias,
                                  float* __restrict__ out) {
    constexpr int HD  = H * D;
    constexpr int HD4 = HD / 4;
    int warp = (blockIdx.x * blockDim.x + threadIdx.x) >> 5;
    int lane = threadIdx.x & 31;
    int g    = lane / HD4;
    int sub  = lane - g * HD4;
    int node = warp * GPW + g;
    if (g >= GPW || node >= NN) return;

    const int h    = (4 * sub) / D;
    const float er_d = __ldg(&er[node * H + h]);
    const int e0 = g_rowptr[node];
    const int e1 = g_rowptr[node + 1];

    float ssum = 0.f;
    float ax = 0.f, ay = 0.f, az = 0.f, aw = 0.f;
#pragma unroll 4
    for (int e = e0; e < e1; e++) {
        int s   = __ldg(&g_colsrc[e]);
        float v = __ldg(&el[s * H + h]) + er_d;
        v = v > 0.f ? v : 0.2f * v;
        float p = __expf(v);
        uint2 raw = __ldg((const uint2*)(feat + (size_t)s * HD + 4 * sub));
        float2 f01 = __half22float2(*(const __half2*)&raw.x);
        float2 f23 = __half22float2(*(const __half2*)&raw.y);
        ax += p * f01.x;
        ay += p * f01.y;
        az += p * f23.x;
        aw += p * f23.y;
        ssum += p;
    }
    float inv = __frcp_rn(ssum);
    float4 o;
    o.x = ax * inv + __ldg(&bias[4 * sub + 0]);
    o.y = ay * inv + __ldg(&bias[4 * sub + 1]);
    o.z = az * inv + __ldg(&bias[4 * sub + 2]);
    o.w = aw * inv + __ldg(&bias[4 * sub + 3]);
    *(float4*)(out + (size_t)node * HD + 4 * sub) = o;
}

// ---------------- launcher ---------------------------------------------------
extern "C" void kernel_launch(void* const* d_in, const int* in_sizes, int n_in,
                              void* d_out, int out_size) {
    const float* in_feat = (const float*)d_in[0];
    const void*  src     = d_in[1];
    const void*  dst     = d_in[2];
    const float* W0 = (const float*)d_in[3];
    const float* al0 = (const float*)d_in[4];
    const float* ar0 = (const float*)d_in[5];
    const float* b0 = (const float*)d_in[6];
    const float* W1 = (const float*)d_in[7];
    const float* al1 = (const float*)d_in[8];
    const float* ar1 = (const float*)d_in[9];
    const float* b1 = (const float*)d_in[10];
    const float* W2 = (const float*)d_in[11];
    const float* al2 = (const float*)d_in[12];
    const float* ar2 = (const float*)d_in[13];
    const float* b2 = (const float*)d_in[14];
    float* out = (float*)d_out;

    __half* feat_p;
    float *h0_p, *h1_p, *el_p, *er_p;
    int* count_p;
    cudaGetSymbolAddress((void**)&feat_p, g_feat16);
    cudaGetSymbolAddress((void**)&h0_p, g_h0);
    cudaGetSymbolAddress((void**)&h1_p, g_h1);
    cudaGetSymbolAddress((void**)&el_p, g_el);
    cudaGetSymbolAddress((void**)&er_p, g_er);
    cudaGetSymbolAddress((void**)&count_p, g_count);

    constexpr int SMEM_L0 = (128 * 128 + 64 * 128) * 4;  // 96 KB
    constexpr int SMEM_L1 = (128 * 64 + 64 * 128) * 4;   // 64 KB
    cudaFuncSetAttribute(gemm_tiled_kernel<128, 128, 8, 32, 8, 2>,
                         cudaFuncAttributeMaxDynamicSharedMemorySize, SMEM_L0);
    cudaFuncSetAttribute(gemm_tiled_kernel<128, 64, 4, 16, 16, 1>,
                         cudaFuncAttributeMaxDynamicSharedMemorySize, SMEM_L1);

    // ---- try to insert GEMM0 as a root graph node (runs parallel to CSR) ----
    bool manual = false;
    cudaGraphNode_t gemm0_node;
    {
        cudaStreamCaptureStatus st = cudaStreamCaptureStatusNone;
        cudaGraph_t cgraph = nullptr;
        const cudaGraphNode_t* cdeps = nullptr;
        const cudaGraphEdgeData* cedges = nullptr;
        size_t nd = 0;
        unsigned long long cid = 0;
        if (cudaStreamGetCaptureInfo((cudaStream_t)0, &st, &cid, &cgraph,
                                     &cdeps, &cedges, &nd) == cudaSuccess &&
            st == cudaStreamCaptureStatusActive && cgraph != nullptr) {
            cudaKernelNodeParams p = {};
            const float* a_in = in_feat;
            const float* a_W = W0;
            const float* a_al = al0;
            const float* a_ar = ar0;
            __half* a_feat = feat_p;
            float* a_el = el_p;
            float* a_er = er_p;
            void* args[7] = {&a_in, &a_W, &a_al, &a_ar, &a_feat, &a_el, &a_er};
            p.func = (void*)gemm_tiled_kernel<128, 128, 8, 32, 8, 2>;
            p.gridDim = dim3((NN + 63) / 64, 1, 1);
            p.blockDim = dim3(256, 1, 1);
            p.sharedMemBytes = SMEM_L0;
            p.kernelParams = args;
            p.extra = nullptr;
            if (cudaGraphAddKernelNode(&gemm0_node, cgraph, nullptr, 0, &p)
                    == cudaSuccess)
                manual = true;
        }
    }

    // ---- CSR build chain (in-stream; overlaps with GEMM0) ----
    detect_kernel<<<1, 1>>>((const unsigned*)src, (const unsigned*)dst);
    cudaMemsetAsync(count_p, 0, NN * sizeof(int));
    hist_kernel<<<(EE + 255) / 256, 256>>>(src, dst);
    int nb = (NN + 1023) / 1024;
    scan_block_kernel<<<nb, 1024>>>();
    scan_add_kernel<<<(NN + 255) / 256, 256>>>(nb);
    scatter_kernel<<<(EE + 255) / 256, 256>>>();

    // ---- join GEMM0 into the stream (or launch it here if not capturing) ----
    if (manual) {
        cudaStreamUpdateCaptureDependencies((cudaStream_t)0, &gemm0_node,
                                            nullptr, 1,
                                            cudaStreamAddCaptureDependencies);
    } else {
        gemm_tiled_kernel<128, 128, 8, 32, 8, 2>
            <<<(NN + 63) / 64, 256, SMEM_L0>>>(in_feat, W0, al0, ar0,
                                               feat_p, el_p, er_p);
    }

    // ---- layer 0 edge phase: warp per node (GPW=1, as R7) ----
    fused_attn_kernel<2, 64, 1>
        <<<(NN * 32 + 255) / 256, 256>>>(feat_p, el_p, er_p, b0, h0_p);

    // ---- layer 1: 128 -> 1 head x 64 ----
    gemm_tiled_kernel<128, 64, 4, 16, 16, 1>
        <<<(NN + 63) / 64, 256, SMEM_L1>>>(h0_p, W1, al1, ar1, feat_p, el_p, er_p);
    {
        int warps = (NN + 1) / 2;
        fused_attn_kernel<1, 64, 2>
            <<<(warps * 32 + 255) / 256, 256>>>(feat_p, el_p, er_p, b1, h1_p);
    }

    // ---- layer 2: 64 -> 1 head x 40 -> d_out ----
    gemm_feat_kernel<<<(NN + 7) / 8, 256>>>(h1_p, W2, al2, ar2, feat_p, el_p, er_p, 64, 1, 40);
    {
        int warps = (NN + 2) / 3;
        fused_attn_kernel<1, 40, 3>
            <<<(warps * 32 + 255) / 256, 256>>>(feat_p, el_p, er_p, b2, out);
    }
}